// round 11
// baseline (speedup 1.0000x reference)
#include <cuda_runtime.h>
#include <cstdint>

#define NT 400000
#define ND 200000

typedef unsigned long long u64;

// ---------------- static scratch (referenced ONLY from device code) ----------------
__device__ __align__(16) float g_to [(size_t)NT * 12];   // tt_to raw sums             19.2MB
__device__ __align__(16) float g_fr [(size_t)NT * 12];   // tt_from raw sums           19.2MB
__device__ __align__(16) float g_dt [(size_t)NT * 8];    // data->tasks raw sums (5)   12.8MB
__device__ __align__(16) float g_td [(size_t)ND * 12];   // tasks->data raw sums        9.6MB
__device__ __align__(16) u64   g_cdevt[NT];              // devices->tasks 8x8bit cnt   3.2MB
__device__ __align__(16) u64   g_cdevd[ND];              // devices->data 8x8bit cnt    1.6MB
__device__ float g_tdev[8 * 12];                         // tasks->devices agg
__device__ float g_ddev[8 * 8];                          // data->devices agg
__device__ __align__(16) float g_xd8[(size_t)ND * 8];    // x_data padded to stride 8   6.4MB

// ---------------- helpers ----------------
__device__ __forceinline__ u64 pack2(float x, float y) {
    u64 r; asm("mov.b64 %0, {%1,%2};" : "=l"(r) : "f"(x), "f"(y)); return r;
}
__device__ __forceinline__ float2 unpack2(u64 v) {
    float2 r; asm("mov.b64 {%0,%1}, %2;" : "=f"(r.x), "=f"(r.y) : "l"(v)); return r;
}
__device__ __forceinline__ void fma2(u64& d, u64 a, u64 b) {  // d = a*b + d (packed f32x2)
    asm("fma.rn.f32x2 %0, %1, %2, %0;" : "+l"(d) : "l"(a), "l"(b));
}
__device__ __forceinline__ void red4(float* p, float a, float b, float c, float d) {
    asm volatile("red.global.add.v4.f32 [%0], {%1,%2,%3,%4};"
                 :: "l"(p), "f"(a), "f"(b), "f"(c), "f"(d) : "memory");
}
__device__ __forceinline__ void red1(float* p, float a) {
    asm volatile("red.global.add.f32 [%0], %1;" :: "l"(p), "f"(a) : "memory");
}
__device__ __forceinline__ void redu64(u64* p, u64 v) {
    asm volatile("red.global.add.u64 [%0], %1;" :: "l"(p), "l"(v) : "memory");
}
// evict-first (streaming) int load: edge lists are single-use, keep them out of hot L2
__device__ __forceinline__ int ldcs(const int* p) {
    int v; asm("ld.global.cs.b32 %0, [%1];" : "=r"(v) : "l"(p)); return v;
}

// ---------------- prep: zero scratch + pad x_data ----------------
__global__ void prep(const float* __restrict__ xd) {
    size_t i  = (size_t)blockIdx.x * blockDim.x + threadIdx.x;
    size_t st = (size_t)gridDim.x * blockDim.x;
    float4 z = make_float4(0.f, 0.f, 0.f, 0.f);
    for (size_t j = i; j < (size_t)NT * 3; j += st) ((float4*)g_to)[j] = z;
    for (size_t j = i; j < (size_t)NT * 3; j += st) ((float4*)g_fr)[j] = z;
    for (size_t j = i; j < (size_t)NT * 2; j += st) ((float4*)g_dt)[j] = z;
    for (size_t j = i; j < (size_t)ND * 3; j += st) ((float4*)g_td)[j] = z;
    for (size_t j = i; j < (size_t)NT / 2; j += st) ((float4*)g_cdevt)[j] = z;
    for (size_t j = i; j < (size_t)ND / 2; j += st) ((float4*)g_cdevd)[j] = z;
    if (i < 96) g_tdev[i] = 0.f;
    if (i < 64) g_ddev[i] = 0.f;
    for (size_t j = i; j < (size_t)ND; j += st) {
        const float* r = xd + j * 5;
        float4* o = (float4*)(g_xd8 + j * 8);
        o[0] = make_float4(r[0], r[1], r[2], r[3]);
        o[1] = make_float4(r[4], 0.f, 0.f, 0.f);
    }
}

// ---------------- fused scatter: all 8 relations, one launch ----------------
// heavy segments process 2 edges per thread (512 edges / block) for MLP
__global__ void __launch_bounds__(256, 8) fused_scatter(
    const float* __restrict__ xt,
    const int* __restrict__ e_dt,   int E_dt,
    const int* __restrict__ e_to,   int E_to,
    const int* __restrict__ e_fr,   int E_fr,
    const int* __restrict__ e_td,   int E_td,
    const int* __restrict__ e_devt, int E_devt,
    const int* __restrict__ e_devd, int E_devd,
    const int* __restrict__ e_tdev, int E_tdev,
    const int* __restrict__ e_ddev, int E_ddev,
    int b0, int b1, int b2, int b3, int b4, int b5, int b6) {
    int b = blockIdx.x, t = threadIdx.x;

    if (b < b0) {                       // data -> tasks (5-dim, padded src), 2 edges/thread
        int e1 = b * 512 + t, e2 = e1 + 256;
        bool v1 = e1 < E_dt, v2 = e2 < E_dt;
        int s1 = 0, d1 = 0, s2 = 0, d2 = 0;
        if (v1) { s1 = ldcs(e_dt + e1); d1 = ldcs(e_dt + E_dt + e1); }
        if (v2) { s2 = ldcs(e_dt + e2); d2 = ldcs(e_dt + E_dt + e2); }
        float4 A1, B1, A2, B2;
        if (v1) { const float4* x1 = (const float4*)(g_xd8 + (size_t)s1 * 8); A1 = x1[0]; B1 = x1[1]; }
        if (v2) { const float4* x2 = (const float4*)(g_xd8 + (size_t)s2 * 8); A2 = x2[0]; B2 = x2[1]; }
        if (v1) {
            float* p = g_dt + (size_t)d1 * 8;
            red4(p, A1.x, A1.y, A1.z, A1.w); red1(p + 4, B1.x);
        }
        if (v2) {
            float* p = g_dt + (size_t)d2 * 8;
            red4(p, A2.x, A2.y, A2.z, A2.w); red1(p + 4, B2.x);
        }
    } else if (b < b3) {                // 12-dim relations: tto | ttf | td, 2 edges/thread
        const int* ei; int E; float* acc; int rb;
        if (b < b1)      { ei = e_to; E = E_to; acc = g_to; rb = b - b0; }
        else if (b < b2) { ei = e_fr; E = E_fr; acc = g_fr; rb = b - b1; }
        else             { ei = e_td; E = E_td; acc = g_td; rb = b - b2; }
        int e1 = rb * 512 + t, e2 = e1 + 256;
        bool v1 = e1 < E, v2 = e2 < E;
        int s1 = 0, d1 = 0, s2 = 0, d2 = 0;
        if (v1) { s1 = ldcs(ei + e1); d1 = ldcs(ei + E + e1); }
        if (v2) { s2 = ldcs(ei + e2); d2 = ldcs(ei + E + e2); }
        float4 A1, B1, C1, A2, B2, C2;
        if (v1) {
            const float4* x1 = (const float4*)(xt + (size_t)s1 * 12);
            A1 = x1[0]; B1 = x1[1]; C1 = x1[2];
        }
        if (v2) {
            const float4* x2 = (const float4*)(xt + (size_t)s2 * 12);
            A2 = x2[0]; B2 = x2[1]; C2 = x2[2];
        }
        if (v1) {
            float* p = acc + (size_t)d1 * 12;
            red4(p, A1.x, A1.y, A1.z, A1.w);
            red4(p + 4, B1.x, B1.y, B1.z, B1.w);
            red4(p + 8, C1.x, C1.y, C1.z, C1.w);
        }
        if (v2) {
            float* p = acc + (size_t)d2 * 12;
            red4(p, A2.x, A2.y, A2.z, A2.w);
            red4(p + 4, B2.x, B2.y, B2.z, B2.w);
            red4(p + 8, C2.x, C2.y, C2.z, C2.w);
        }
    } else if (b < b4) {                // devices -> tasks : packed count
        int e = (b - b3) * 256 + t;
        if (e >= E_devt) return;
        int s = ldcs(e_devt + e), d = ldcs(e_devt + E_devt + e);
        redu64(&g_cdevt[d], 1ull << (s * 8));
    } else if (b < b5) {                // devices -> data : packed count
        int e = (b - b4) * 256 + t;
        if (e >= E_devd) return;
        int s = ldcs(e_devd + e), d = ldcs(e_devd + E_devd + e);
        redu64(&g_cdevd[d], 1ull << (s * 8));
    } else if (b < b6) {                // tasks -> devices (dst in [0,8))
        __shared__ float acc[96];
        if (t < 96) acc[t] = 0.f;
        __syncthreads();
        int e = (b - b5) * 256 + t;
        if (e < E_tdev) {
            int s = ldcs(e_tdev + e), d = ldcs(e_tdev + E_tdev + e);
            const float4* xr = (const float4*)(xt + (size_t)s * 12);
            float4 A = xr[0], B = xr[1], C = xr[2];
            float* a = acc + d * 12;
            atomicAdd(a + 0, A.x);  atomicAdd(a + 1, A.y);
            atomicAdd(a + 2, A.z);  atomicAdd(a + 3, A.w);
            atomicAdd(a + 4, B.x);  atomicAdd(a + 5, B.y);
            atomicAdd(a + 6, B.z);  atomicAdd(a + 7, B.w);
            atomicAdd(a + 8, C.x);  atomicAdd(a + 9, C.y);
            atomicAdd(a + 10, C.z); atomicAdd(a + 11, C.w);
        }
        __syncthreads();
        if (t < 96 && acc[t] != 0.f) red1(&g_tdev[t], acc[t]);
    } else {                            // data -> devices (5-dim)
        __shared__ float acc[64];
        if (t < 64) acc[t] = 0.f;
        __syncthreads();
        int e = (b - b6) * 256 + t;
        if (e < E_ddev) {
            int s = ldcs(e_ddev + e), d = ldcs(e_ddev + E_ddev + e);
            const float4* xr = (const float4*)(g_xd8 + (size_t)s * 8);
            float4 A = xr[0], B = xr[1];
            float* a = acc + d * 8;
            atomicAdd(a + 0, A.x); atomicAdd(a + 1, A.y);
            atomicAdd(a + 2, A.z); atomicAdd(a + 3, A.w);
            atomicAdd(a + 4, B.x);
        }
        __syncthreads();
        if (t < 64 && acc[t] != 0.f) red1(&g_ddev[t], acc[t]);
    }
}

// ---------------- LN + leaky relu + store ----------------
__device__ __forceinline__ void ln_act_store(float* a, const float* gam, const float* bet,
                                             float* outp) {
    float mu = 0.f;
#pragma unroll
    for (int h = 0; h < 16; h++) mu += a[h];
    mu *= (1.f / 16.f);
    float var = 0.f;
#pragma unroll
    for (int h = 0; h < 16; h++) { float z = a[h] - mu; var += z * z; }
    var *= (1.f / 16.f);
    float inv = rsqrtf(var + 1e-5f);
    float4 o[4];
    float* of = (float*)o;
#pragma unroll
    for (int h = 0; h < 16; h++) {
        float y = (a[h] - mu) * inv * gam[h] + bet[h];
        of[h] = (y > 0.f) ? y : 0.01f * y;
    }
    float4* op = (float4*)outp;
#pragma unroll
    for (int q = 0; q < 4; q++) op[q] = o[q];
}

#define NBT ((NT + 255) / 256)   // 1563
#define NBD ((ND + 255) / 256)   // 782

// ---------------- fused node pass: tasks | data | devices ----------------
__global__ void fused_node(const float* __restrict__ xt,
                           const float* __restrict__ xv,
                           const float* __restrict__ W_rel5,
                           const float* __restrict__ W_rel12,
                           const float* __restrict__ b_rel,
                           const float* __restrict__ W_root5,
                           const float* __restrict__ W_root12,
                           const float* __restrict__ ln_g,
                           const float* __restrict__ ln_b,
                           float* __restrict__ out) {
    __shared__ __align__(16) u64 sm[392];
    __shared__ float smf[48];
    int bb = blockIdx.x, t = threadIdx.x;

    if (bb < NBT) {
        // ---- tasks ----
        u64* sW5  = sm;          // 40  : W_rel5[0]
        u64* sYd  = sm + 40;     // 64  : y_devt = x_dev @ W_rel12[2]  (8 x 16)
        u64* sWto = sm + 104;    // 96  : W_rel12[4]
        u64* sWfr = sm + 200;    // 96  : W_rel12[5]
        u64* sWrt = sm + 296;    // 96  : sum of W_root12[0,2,4,5]
        if (t < 40) sW5[t] = pack2(W_rel5[2 * t], W_rel5[2 * t + 1]);
        if (t < 96) {
            sWto[t] = pack2(W_rel12[4 * 192 + 2 * t], W_rel12[4 * 192 + 2 * t + 1]);
            sWfr[t] = pack2(W_rel12[5 * 192 + 2 * t], W_rel12[5 * 192 + 2 * t + 1]);
            float w0 = W_root12[2 * t] + W_root12[2 * 192 + 2 * t] +
                       W_root12[4 * 192 + 2 * t] + W_root12[5 * 192 + 2 * t];
            float w1 = W_root12[2 * t + 1] + W_root12[2 * 192 + 2 * t + 1] +
                       W_root12[4 * 192 + 2 * t + 1] + W_root12[5 * 192 + 2 * t + 1];
            sWrt[t] = pack2(w0, w1);
        }
        if (t < 64) {
            int n = t >> 3, h0 = (t & 7) * 2;
            float y0 = 0.f, y1 = 0.f;
#pragma unroll
            for (int d = 0; d < 12; d++) {
                float xvv = xv[n * 12 + d];
                y0 += xvv * W_rel12[2 * 192 + d * 16 + h0];
                y1 += xvv * W_rel12[2 * 192 + d * 16 + h0 + 1];
            }
            sYd[t] = pack2(y0, y1);
        }
        if (t < 16) {
            smf[t]      = b_rel[t] + b_rel[3 * 16 + t] + b_rel[6 * 16 + t] + b_rel[7 * 16 + t];
            smf[16 + t] = ln_g[t];
            smf[32 + t] = ln_b[t];
        }
        __syncthreads();
        int n = bb * 256 + t;
        if (n >= NT) return;

        u64 ac[8];
#pragma unroll
        for (int j = 0; j < 8; j++) ac[j] = pack2(smf[2 * j], smf[2 * j + 1]);

        // dt (5-dim raw sums)
        {
            const float4* rp = (const float4*)(g_dt + (size_t)n * 8);
            float4 A = rp[0], B = rp[1];
            float a[5] = {A.x, A.y, A.z, A.w, B.x};
#pragma unroll
            for (int d = 0; d < 5; d++) {
                u64 vv = pack2(a[d], a[d]);
#pragma unroll
                for (int j = 0; j < 8; j++) fma2(ac[j], vv, sW5[d * 8 + j]);
            }
        }
        // devt counts
        {
            u64 c = g_cdevt[n];
            if (c) {
#pragma unroll
                for (int s = 0; s < 8; s++) {
                    float cs = (float)((c >> (8 * s)) & 0xFF);
                    if (cs != 0.f) {
                        u64 vv = pack2(cs, cs);
#pragma unroll
                        for (int j = 0; j < 8; j++) fma2(ac[j], vv, sYd[s * 8 + j]);
                    }
                }
            }
        }
        // tt_to raw sums (stride 12)
        {
            const float4* rp = (const float4*)(g_to + (size_t)n * 12);
            float4 A = rp[0], B = rp[1], C = rp[2];
            float a[12] = {A.x, A.y, A.z, A.w, B.x, B.y, B.z, B.w, C.x, C.y, C.z, C.w};
#pragma unroll
            for (int d = 0; d < 12; d++) {
                u64 vv = pack2(a[d], a[d]);
#pragma unroll
                for (int j = 0; j < 8; j++) fma2(ac[j], vv, sWto[d * 8 + j]);
            }
        }
        // tt_from raw sums (stride 12)
        {
            const float4* rp = (const float4*)(g_fr + (size_t)n * 12);
            float4 A = rp[0], B = rp[1], C = rp[2];
            float a[12] = {A.x, A.y, A.z, A.w, B.x, B.y, B.z, B.w, C.x, C.y, C.z, C.w};
#pragma unroll
            for (int d = 0; d < 12; d++) {
                u64 vv = pack2(a[d], a[d]);
#pragma unroll
                for (int j = 0; j < 8; j++) fma2(ac[j], vv, sWfr[d * 8 + j]);
            }
        }
        // root
        {
            const float4* rp = (const float4*)(xt + (size_t)n * 12);
            float4 A = rp[0], B = rp[1], C = rp[2];
            float a[12] = {A.x, A.y, A.z, A.w, B.x, B.y, B.z, B.w, C.x, C.y, C.z, C.w};
#pragma unroll
            for (int d = 0; d < 12; d++) {
                u64 vv = pack2(a[d], a[d]);
#pragma unroll
                for (int j = 0; j < 8; j++) fma2(ac[j], vv, sWrt[d * 8 + j]);
            }
        }
        float av[16];
#pragma unroll
        for (int j = 0; j < 8; j++) {
            float2 f = unpack2(ac[j]);
            av[2 * j] = f.x; av[2 * j + 1] = f.y;
        }
        ln_act_store(av, smf + 16, smf + 32, out + (size_t)n * 16);

    } else if (bb < NBT + NBD) {
        // ---- data ----
        u64* sWtd  = sm;         // 96 : W_rel12[0]
        u64* sYdd  = sm + 96;    // 64 : y_devd = x_dev @ W_rel12[3]
        u64* sWrt5 = sm + 160;   // 40 : W_root5[0] + W_root5[1]
        if (t < 96) sWtd[t] = pack2(W_rel12[2 * t], W_rel12[2 * t + 1]);
        if (t < 64) {
            int n = t >> 3, h0 = (t & 7) * 2;
            float y0 = 0.f, y1 = 0.f;
#pragma unroll
            for (int d = 0; d < 12; d++) {
                float xvv = xv[n * 12 + d];
                y0 += xvv * W_rel12[3 * 192 + d * 16 + h0];
                y1 += xvv * W_rel12[3 * 192 + d * 16 + h0 + 1];
            }
            sYdd[t] = pack2(y0, y1);
        }
        if (t < 40) {
            float w0 = W_root5[2 * t]     + W_root5[80 + 2 * t];
            float w1 = W_root5[2 * t + 1] + W_root5[80 + 2 * t + 1];
            sWrt5[t] = pack2(w0, w1);
        }
        if (t < 16) {
            smf[t]      = b_rel[16 + t] + b_rel[5 * 16 + t];
            smf[16 + t] = ln_g[16 + t];
            smf[32 + t] = ln_b[16 + t];
        }
        __syncthreads();
        int n = (bb - NBT) * 256 + t;
        if (n >= ND) return;

        u64 ac[8];
#pragma unroll
        for (int j = 0; j < 8; j++) ac[j] = pack2(smf[2 * j], smf[2 * j + 1]);

        // td raw sums (stride 12)
        {
            const float4* rp = (const float4*)(g_td + (size_t)n * 12);
            float4 A = rp[0], B = rp[1], C = rp[2];
            float a[12] = {A.x, A.y, A.z, A.w, B.x, B.y, B.z, B.w, C.x, C.y, C.z, C.w};
#pragma unroll
            for (int d = 0; d < 12; d++) {
                u64 vv = pack2(a[d], a[d]);
#pragma unroll
                for (int j = 0; j < 8; j++) fma2(ac[j], vv, sWtd[d * 8 + j]);
            }
        }
        // devd counts
        {
            u64 c = g_cdevd[n];
            if (c) {
#pragma unroll
                for (int s = 0; s < 8; s++) {
                    float cs = (float)((c >> (8 * s)) & 0xFF);
                    if (cs != 0.f) {
                        u64 vv = pack2(cs, cs);
#pragma unroll
                        for (int j = 0; j < 8; j++) fma2(ac[j], vv, sYdd[s * 8 + j]);
                    }
                }
            }
        }
        // root (5-dim, padded copy)
        {
            const float4* rp = (const float4*)(g_xd8 + (size_t)n * 8);
            float4 A = rp[0], B = rp[1];
            float a[5] = {A.x, A.y, A.z, A.w, B.x};
#pragma unroll
            for (int d = 0; d < 5; d++) {
                u64 vv = pack2(a[d], a[d]);
#pragma unroll
                for (int j = 0; j < 8; j++) fma2(ac[j], vv, sWrt5[d * 8 + j]);
            }
        }
        float av[16];
#pragma unroll
        for (int j = 0; j < 8; j++) {
            float2 f = unpack2(ac[j]);
            av[2 * j] = f.x; av[2 * j + 1] = f.y;
        }
        ln_act_store(av, smf + 16, smf + 32, out + (size_t)(NT + n) * 16);

    } else {
        // ---- devices (8 nodes) ----
        int n = t;
        if (n >= 8) return;
        float acc[16];
#pragma unroll
        for (int h = 0; h < 16; h++) acc[h] = b_rel[2 * 16 + h] + b_rel[4 * 16 + h];
        for (int d = 0; d < 12; d++) {
            float v = g_tdev[n * 12 + d];
#pragma unroll
            for (int h = 0; h < 16; h++) acc[h] += v * W_rel12[1 * 192 + d * 16 + h];
        }
        for (int d = 0; d < 5; d++) {
            float v = g_ddev[n * 8 + d];
#pragma unroll
            for (int h = 0; h < 16; h++) acc[h] += v * W_rel5[80 + d * 16 + h];
        }
        for (int d = 0; d < 12; d++) {
            float v = xv[n * 12 + d];
#pragma unroll
            for (int h = 0; h < 16; h++)
                acc[h] += v * (W_root12[1 * 192 + d * 16 + h] + W_root12[3 * 192 + d * 16 + h]);
        }
        float gam[16], bet[16];
#pragma unroll
        for (int h = 0; h < 16; h++) { gam[h] = ln_g[2 * 16 + h]; bet[h] = ln_b[2 * 16 + h]; }
        ln_act_store(acc, gam, bet, out + (size_t)(NT + ND + n) * 16);
    }
}

// ---------------- launch ----------------
extern "C" void kernel_launch(void* const* d_in, const int* in_sizes, int n_in,
                              void* d_out, int out_size) {
    const float* x_tasks = (const float*)d_in[0];
    const float* x_data  = (const float*)d_in[1];
    const float* x_dev   = (const float*)d_in[2];
    const int* ei_dt   = (const int*)d_in[3];   // data  -> tasks
    const int* ei_td   = (const int*)d_in[4];   // tasks -> data
    const int* ei_tdev = (const int*)d_in[5];   // tasks -> devices
    const int* ei_devt = (const int*)d_in[6];   // devices -> tasks
    const int* ei_ddev = (const int*)d_in[7];   // data  -> devices
    const int* ei_devd = (const int*)d_in[8];   // devices -> data
    const int* ei_tto  = (const int*)d_in[9];   // tasks -> tasks (to)
    const int* ei_ttf  = (const int*)d_in[10];  // tasks -> tasks (from)
    const float* W_rel5   = (const float*)d_in[11];
    const float* W_rel12  = (const float*)d_in[12];
    const float* b_rel    = (const float*)d_in[13];
    const float* W_root5  = (const float*)d_in[14];
    const float* W_root12 = (const float*)d_in[15];
    const float* ln_g     = (const float*)d_in[16];
    const float* ln_b     = (const float*)d_in[17];
    float* out = (float*)d_out;

    int E_dt   = in_sizes[3]  / 2;
    int E_td   = in_sizes[4]  / 2;
    int E_tdev = in_sizes[5]  / 2;
    int E_devt = in_sizes[6]  / 2;
    int E_ddev = in_sizes[7]  / 2;
    int E_devd = in_sizes[8]  / 2;
    int E_tto  = in_sizes[9]  / 2;
    int E_ttf  = in_sizes[10] / 2;

    auto cdiv = [](int a, int b) { return (a + b - 1) / b; };
    int b0 = cdiv(E_dt, 512);
    int b1 = b0 + cdiv(E_tto, 512);
    int b2 = b1 + cdiv(E_ttf, 512);
    int b3 = b2 + cdiv(E_td, 512);
    int b4 = b3 + cdiv(E_devt, 256);
    int b5 = b4 + cdiv(E_devd, 256);
    int b6 = b5 + cdiv(E_tdev, 256);
    int b7 = b6 + cdiv(E_ddev, 256);

    prep<<<1024, 256>>>(x_data);
    fused_scatter<<<b7, 256>>>(x_tasks,
                               ei_dt, E_dt, ei_tto, E_tto, ei_ttf, E_ttf, ei_td, E_td,
                               ei_devt, E_devt, ei_devd, E_devd,
                               ei_tdev, E_tdev, ei_ddev, E_ddev,
                               b0, b1, b2, b3, b4, b5, b6);
    fused_node<<<NBT + NBD + 1, 256>>>(x_tasks, x_dev, W_rel5, W_rel12, b_rel,
                                       W_root5, W_root12, ln_g, ln_b, out);
}

// round 12
// speedup vs baseline: 1.0332x; 1.0332x over previous
#include <cuda_runtime.h>
#include <cuda_fp16.h>
#include <cstdint>

#define NT 400000
#define ND 200000

typedef unsigned long long u64;

// ---------------- static scratch (referenced ONLY from device code) ----------------
__device__ __align__(16) float g_to [(size_t)NT * 12];   // tt_to raw sums             19.2MB
__device__ __align__(16) float g_fr [(size_t)NT * 12];   // tt_from raw sums           19.2MB
__device__ __align__(16) float g_dt [(size_t)NT * 8];    // data->tasks raw sums (5)   12.8MB
__device__ __align__(16) float g_td [(size_t)ND * 12];   // tasks->data raw sums        9.6MB
__device__ __align__(16) u64   g_cdevt[NT];              // devices->tasks 8x8bit cnt   3.2MB
__device__ __align__(16) u64   g_cdevd[ND];              // devices->data 8x8bit cnt    1.6MB
__device__ float g_tdev[8 * 12];                         // tasks->devices agg
__device__ float g_ddev[8 * 8];                          // data->devices agg
__device__ __align__(16) float  g_xd8 [(size_t)ND * 8];  // x_data padded fp32          6.4MB
__device__ __align__(16) __half g_xt16[(size_t)NT * 16]; // x_tasks fp16, stride 16h   12.8MB
__device__ __align__(16) __half g_xd16[(size_t)ND * 8];  // x_data fp16, stride 8h      3.2MB

// ---------------- helpers ----------------
__device__ __forceinline__ u64 pack2(float x, float y) {
    u64 r; asm("mov.b64 %0, {%1,%2};" : "=l"(r) : "f"(x), "f"(y)); return r;
}
__device__ __forceinline__ float2 unpack2(u64 v) {
    float2 r; asm("mov.b64 {%0,%1}, %2;" : "=f"(r.x), "=f"(r.y) : "l"(v)); return r;
}
__device__ __forceinline__ void fma2(u64& d, u64 a, u64 b) {  // d = a*b + d (packed f32x2)
    asm("fma.rn.f32x2 %0, %1, %2, %0;" : "+l"(d) : "l"(a), "l"(b));
}
__device__ __forceinline__ void red4(float* p, float a, float b, float c, float d) {
    asm volatile("red.global.add.v4.f32 [%0], {%1,%2,%3,%4};"
                 :: "l"(p), "f"(a), "f"(b), "f"(c), "f"(d) : "memory");
}
__device__ __forceinline__ void red1(float* p, float a) {
    asm volatile("red.global.add.f32 [%0], %1;" :: "l"(p), "f"(a) : "memory");
}
__device__ __forceinline__ void redu64(u64* p, u64 v) {
    asm volatile("red.global.add.u64 [%0], %1;" :: "l"(p), "l"(v) : "memory");
}
__device__ __forceinline__ unsigned h2u(__half2 h) {
    return *reinterpret_cast<unsigned*>(&h);
}
__device__ __forceinline__ float2 u2f(unsigned u) {
    __half2 h = *reinterpret_cast<__half2*>(&u);
    return __half22float2(h);
}

// ---------------- prep: zero scratch + build fp16/pad copies ----------------
__global__ void prep(const float* __restrict__ xd, const float* __restrict__ xt) {
    size_t i  = (size_t)blockIdx.x * blockDim.x + threadIdx.x;
    size_t st = (size_t)gridDim.x * blockDim.x;
    float4 z = make_float4(0.f, 0.f, 0.f, 0.f);
    for (size_t j = i; j < (size_t)NT * 3; j += st) ((float4*)g_to)[j] = z;
    for (size_t j = i; j < (size_t)NT * 3; j += st) ((float4*)g_fr)[j] = z;
    for (size_t j = i; j < (size_t)NT * 2; j += st) ((float4*)g_dt)[j] = z;
    for (size_t j = i; j < (size_t)ND * 3; j += st) ((float4*)g_td)[j] = z;
    for (size_t j = i; j < (size_t)NT / 2; j += st) ((float4*)g_cdevt)[j] = z;
    for (size_t j = i; j < (size_t)ND / 2; j += st) ((float4*)g_cdevd)[j] = z;
    if (i < 96) g_tdev[i] = 0.f;
    if (i < 64) g_ddev[i] = 0.f;
    // x_data: fp32 padded copy + fp16 copy (stride 8 halves = 16B)
    for (size_t j = i; j < (size_t)ND; j += st) {
        const float* r = xd + j * 5;
        float r0 = r[0], r1 = r[1], r2 = r[2], r3 = r[3], r4 = r[4];
        float4* o = (float4*)(g_xd8 + j * 8);
        o[0] = make_float4(r0, r1, r2, r3);
        o[1] = make_float4(r4, 0.f, 0.f, 0.f);
        uint4 u;
        u.x = h2u(__floats2half2_rn(r0, r1));
        u.y = h2u(__floats2half2_rn(r2, r3));
        u.z = h2u(__floats2half2_rn(r4, 0.f));
        u.w = 0;
        *(uint4*)(g_xd16 + j * 8) = u;
    }
    // x_tasks: fp16 copy (stride 16 halves = 32B, 12 used)
    for (size_t j = i; j < (size_t)NT; j += st) {
        const float4* r = (const float4*)(xt + j * 12);
        float4 a = r[0], b = r[1], c = r[2];
        uint4 ua;
        ua.x = h2u(__floats2half2_rn(a.x, a.y));
        ua.y = h2u(__floats2half2_rn(a.z, a.w));
        ua.z = h2u(__floats2half2_rn(b.x, b.y));
        ua.w = h2u(__floats2half2_rn(b.z, b.w));
        uint2 ub;
        ub.x = h2u(__floats2half2_rn(c.x, c.y));
        ub.y = h2u(__floats2half2_rn(c.z, c.w));
        __half* row = g_xt16 + j * 16;
        *(uint4*)row = ua;
        *(uint2*)(row + 8) = ub;
    }
}

// gather a 12-dim fp16 row into 12 floats (2 loads)
__device__ __forceinline__ void gather12h(int s, float* f) {
    const __half* row = g_xt16 + (size_t)s * 16;
    uint4 ua = *(const uint4*)row;
    uint2 ub = *(const uint2*)(row + 8);
    float2 f0 = u2f(ua.x), f1 = u2f(ua.y), f2 = u2f(ua.z);
    float2 f3 = u2f(ua.w), f4 = u2f(ub.x), f5 = u2f(ub.y);
    f[0] = f0.x; f[1] = f0.y; f[2]  = f1.x; f[3]  = f1.y;
    f[4] = f2.x; f[5] = f2.y; f[6]  = f3.x; f[7]  = f3.y;
    f[8] = f4.x; f[9] = f4.y; f[10] = f5.x; f[11] = f5.y;
}

// ---------------- fused scatter: all 8 relations, one launch (thread-per-edge) ----------------
__global__ void fused_scatter(
    const int* __restrict__ e_dt,   int E_dt,
    const int* __restrict__ e_to,   int E_to,
    const int* __restrict__ e_fr,   int E_fr,
    const int* __restrict__ e_td,   int E_td,
    const int* __restrict__ e_devt, int E_devt,
    const int* __restrict__ e_devd, int E_devd,
    const int* __restrict__ e_tdev, int E_tdev,
    const int* __restrict__ e_ddev, int E_ddev,
    int b0, int b1, int b2, int b3, int b4, int b5, int b6) {
    int b = blockIdx.x, t = threadIdx.x;

    if (b < b0) {                       // data -> tasks (5-dim fp16 src, 1 load)
        int e = b * 256 + t;
        if (e >= E_dt) return;
        int s = e_dt[e], d = e_dt[E_dt + e];
        uint4 u = *(const uint4*)(g_xd16 + (size_t)s * 8);
        float2 f0 = u2f(u.x), f1 = u2f(u.y), f2 = u2f(u.z);
        float* p = g_dt + (size_t)d * 8;
        red4(p, f0.x, f0.y, f1.x, f1.y);
        red1(p + 4, f2.x);
    } else if (b < b3) {                // 12-dim relations: tto | ttf | td (fp16 src, 2 loads)
        const int* ei; int E; float* acc; int rb;
        if (b < b1)      { ei = e_to; E = E_to; acc = g_to; rb = b - b0; }
        else if (b < b2) { ei = e_fr; E = E_fr; acc = g_fr; rb = b - b1; }
        else             { ei = e_td; E = E_td; acc = g_td; rb = b - b2; }
        int e = rb * 256 + t;
        if (e >= E) return;
        int s = ei[e], d = ei[E + e];
        float f[12];
        gather12h(s, f);
        float* p = acc + (size_t)d * 12;
        red4(p,     f[0], f[1], f[2],  f[3]);
        red4(p + 4, f[4], f[5], f[6],  f[7]);
        red4(p + 8, f[8], f[9], f[10], f[11]);
    } else if (b < b4) {                // devices -> tasks : packed count
        int e = (b - b3) * 256 + t;
        if (e >= E_devt) return;
        int s = e_devt[e], d = e_devt[E_devt + e];
        redu64(&g_cdevt[d], 1ull << (s * 8));
    } else if (b < b5) {                // devices -> data : packed count
        int e = (b - b4) * 256 + t;
        if (e >= E_devd) return;
        int s = e_devd[e], d = e_devd[E_devd + e];
        redu64(&g_cdevd[d], 1ull << (s * 8));
    } else if (b < b6) {                // tasks -> devices (dst in [0,8))
        __shared__ float acc[96];
        if (t < 96) acc[t] = 0.f;
        __syncthreads();
        int e = (b - b5) * 256 + t;
        if (e < E_tdev) {
            int s = e_tdev[e], d = e_tdev[E_tdev + e];
            float f[12];
            gather12h(s, f);
            float* a = acc + d * 12;
#pragma unroll
            for (int k = 0; k < 12; k++) atomicAdd(a + k, f[k]);
        }
        __syncthreads();
        if (t < 96 && acc[t] != 0.f) red1(&g_tdev[t], acc[t]);
    } else {                            // data -> devices (5-dim)
        __shared__ float acc[64];
        if (t < 64) acc[t] = 0.f;
        __syncthreads();
        int e = (b - b6) * 256 + t;
        if (e < E_ddev) {
            int s = e_ddev[e], d = e_ddev[E_ddev + e];
            uint4 u = *(const uint4*)(g_xd16 + (size_t)s * 8);
            float2 f0 = u2f(u.x), f1 = u2f(u.y), f2 = u2f(u.z);
            float* a = acc + d * 8;
            atomicAdd(a + 0, f0.x); atomicAdd(a + 1, f0.y);
            atomicAdd(a + 2, f1.x); atomicAdd(a + 3, f1.y);
            atomicAdd(a + 4, f2.x);
        }
        __syncthreads();
        if (t < 64 && acc[t] != 0.f) red1(&g_ddev[t], acc[t]);
    }
}

// ---------------- LN + leaky relu + store ----------------
__device__ __forceinline__ void ln_act_store(float* a, const float* gam, const float* bet,
                                             float* outp) {
    float mu = 0.f;
#pragma unroll
    for (int h = 0; h < 16; h++) mu += a[h];
    mu *= (1.f / 16.f);
    float var = 0.f;
#pragma unroll
    for (int h = 0; h < 16; h++) { float z = a[h] - mu; var += z * z; }
    var *= (1.f / 16.f);
    float inv = rsqrtf(var + 1e-5f);
    float4 o[4];
    float* of = (float*)o;
#pragma unroll
    for (int h = 0; h < 16; h++) {
        float y = (a[h] - mu) * inv * gam[h] + bet[h];
        of[h] = (y > 0.f) ? y : 0.01f * y;
    }
    float4* op = (float4*)outp;
#pragma unroll
    for (int q = 0; q < 4; q++) op[q] = o[q];
}

#define NBT ((NT + 255) / 256)   // 1563
#define NBD ((ND + 255) / 256)   // 782

// ---------------- fused node pass: tasks | data | devices ----------------
__global__ void fused_node(const float* __restrict__ xt,
                           const float* __restrict__ xv,
                           const float* __restrict__ W_rel5,
                           const float* __restrict__ W_rel12,
                           const float* __restrict__ b_rel,
                           const float* __restrict__ W_root5,
                           const float* __restrict__ W_root12,
                           const float* __restrict__ ln_g,
                           const float* __restrict__ ln_b,
                           float* __restrict__ out) {
    __shared__ __align__(16) u64 sm[392];
    __shared__ float smf[48];
    int bb = blockIdx.x, t = threadIdx.x;

    if (bb < NBT) {
        // ---- tasks ----
        u64* sW5  = sm;          // 40  : W_rel5[0]
        u64* sYd  = sm + 40;     // 64  : y_devt = x_dev @ W_rel12[2]  (8 x 16)
        u64* sWto = sm + 104;    // 96  : W_rel12[4]
        u64* sWfr = sm + 200;    // 96  : W_rel12[5]
        u64* sWrt = sm + 296;    // 96  : sum of W_root12[0,2,4,5]
        if (t < 40) sW5[t] = pack2(W_rel5[2 * t], W_rel5[2 * t + 1]);
        if (t < 96) {
            sWto[t] = pack2(W_rel12[4 * 192 + 2 * t], W_rel12[4 * 192 + 2 * t + 1]);
            sWfr[t] = pack2(W_rel12[5 * 192 + 2 * t], W_rel12[5 * 192 + 2 * t + 1]);
            float w0 = W_root12[2 * t] + W_root12[2 * 192 + 2 * t] +
                       W_root12[4 * 192 + 2 * t] + W_root12[5 * 192 + 2 * t];
            float w1 = W_root12[2 * t + 1] + W_root12[2 * 192 + 2 * t + 1] +
                       W_root12[4 * 192 + 2 * t + 1] + W_root12[5 * 192 + 2 * t + 1];
            sWrt[t] = pack2(w0, w1);
        }
        if (t < 64) {
            int n = t >> 3, h0 = (t & 7) * 2;
            float y0 = 0.f, y1 = 0.f;
#pragma unroll
            for (int d = 0; d < 12; d++) {
                float xvv = xv[n * 12 + d];
                y0 += xvv * W_rel12[2 * 192 + d * 16 + h0];
                y1 += xvv * W_rel12[2 * 192 + d * 16 + h0 + 1];
            }
            sYd[t] = pack2(y0, y1);
        }
        if (t < 16) {
            smf[t]      = b_rel[t] + b_rel[3 * 16 + t] + b_rel[6 * 16 + t] + b_rel[7 * 16 + t];
            smf[16 + t] = ln_g[t];
            smf[32 + t] = ln_b[t];
        }
        __syncthreads();
        int n = bb * 256 + t;
        if (n >= NT) return;

        u64 ac[8];
#pragma unroll
        for (int j = 0; j < 8; j++) ac[j] = pack2(smf[2 * j], smf[2 * j + 1]);

        // dt (5-dim raw sums)
        {
            const float4* rp = (const float4*)(g_dt + (size_t)n * 8);
            float4 A = rp[0], B = rp[1];
            float a[5] = {A.x, A.y, A.z, A.w, B.x};
#pragma unroll
            for (int d = 0; d < 5; d++) {
                u64 vv = pack2(a[d], a[d]);
#pragma unroll
                for (int j = 0; j < 8; j++) fma2(ac[j], vv, sW5[d * 8 + j]);
            }
        }
        // devt counts
        {
            u64 c = g_cdevt[n];
            if (c) {
#pragma unroll
                for (int s = 0; s < 8; s++) {
                    float cs = (float)((c >> (8 * s)) & 0xFF);
                    if (cs != 0.f) {
                        u64 vv = pack2(cs, cs);
#pragma unroll
                        for (int j = 0; j < 8; j++) fma2(ac[j], vv, sYd[s * 8 + j]);
                    }
                }
            }
        }
        // tt_to raw sums (stride 12)
        {
            const float4* rp = (const float4*)(g_to + (size_t)n * 12);
            float4 A = rp[0], B = rp[1], C = rp[2];
            float a[12] = {A.x, A.y, A.z, A.w, B.x, B.y, B.z, B.w, C.x, C.y, C.z, C.w};
#pragma unroll
            for (int d = 0; d < 12; d++) {
                u64 vv = pack2(a[d], a[d]);
#pragma unroll
                for (int j = 0; j < 8; j++) fma2(ac[j], vv, sWto[d * 8 + j]);
            }
        }
        // tt_from raw sums (stride 12)
        {
            const float4* rp = (const float4*)(g_fr + (size_t)n * 12);
            float4 A = rp[0], B = rp[1], C = rp[2];
            float a[12] = {A.x, A.y, A.z, A.w, B.x, B.y, B.z, B.w, C.x, C.y, C.z, C.w};
#pragma unroll
            for (int d = 0; d < 12; d++) {
                u64 vv = pack2(a[d], a[d]);
#pragma unroll
                for (int j = 0; j < 8; j++) fma2(ac[j], vv, sWfr[d * 8 + j]);
            }
        }
        // root (full fp32)
        {
            const float4* rp = (const float4*)(xt + (size_t)n * 12);
            float4 A = rp[0], B = rp[1], C = rp[2];
            float a[12] = {A.x, A.y, A.z, A.w, B.x, B.y, B.z, B.w, C.x, C.y, C.z, C.w};
#pragma unroll
            for (int d = 0; d < 12; d++) {
                u64 vv = pack2(a[d], a[d]);
#pragma unroll
                for (int j = 0; j < 8; j++) fma2(ac[j], vv, sWrt[d * 8 + j]);
            }
        }
        float av[16];
#pragma unroll
        for (int j = 0; j < 8; j++) {
            float2 f = unpack2(ac[j]);
            av[2 * j] = f.x; av[2 * j + 1] = f.y;
        }
        ln_act_store(av, smf + 16, smf + 32, out + (size_t)n * 16);

    } else if (bb < NBT + NBD) {
        // ---- data ----
        u64* sWtd  = sm;         // 96 : W_rel12[0]
        u64* sYdd  = sm + 96;    // 64 : y_devd = x_dev @ W_rel12[3]
        u64* sWrt5 = sm + 160;   // 40 : W_root5[0] + W_root5[1]
        if (t < 96) sWtd[t] = pack2(W_rel12[2 * t], W_rel12[2 * t + 1]);
        if (t < 64) {
            int n = t >> 3, h0 = (t & 7) * 2;
            float y0 = 0.f, y1 = 0.f;
#pragma unroll
            for (int d = 0; d < 12; d++) {
                float xvv = xv[n * 12 + d];
                y0 += xvv * W_rel12[3 * 192 + d * 16 + h0];
                y1 += xvv * W_rel12[3 * 192 + d * 16 + h0 + 1];
            }
            sYdd[t] = pack2(y0, y1);
        }
        if (t < 40) {
            float w0 = W_root5[2 * t]     + W_root5[80 + 2 * t];
            float w1 = W_root5[2 * t + 1] + W_root5[80 + 2 * t + 1];
            sWrt5[t] = pack2(w0, w1);
        }
        if (t < 16) {
            smf[t]      = b_rel[16 + t] + b_rel[5 * 16 + t];
            smf[16 + t] = ln_g[16 + t];
            smf[32 + t] = ln_b[16 + t];
        }
        __syncthreads();
        int n = (bb - NBT) * 256 + t;
        if (n >= ND) return;

        u64 ac[8];
#pragma unroll
        for (int j = 0; j < 8; j++) ac[j] = pack2(smf[2 * j], smf[2 * j + 1]);

        // td raw sums (stride 12)
        {
            const float4* rp = (const float4*)(g_td + (size_t)n * 12);
            float4 A = rp[0], B = rp[1], C = rp[2];
            float a[12] = {A.x, A.y, A.z, A.w, B.x, B.y, B.z, B.w, C.x, C.y, C.z, C.w};
#pragma unroll
            for (int d = 0; d < 12; d++) {
                u64 vv = pack2(a[d], a[d]);
#pragma unroll
                for (int j = 0; j < 8; j++) fma2(ac[j], vv, sWtd[d * 8 + j]);
            }
        }
        // devd counts
        {
            u64 c = g_cdevd[n];
            if (c) {
#pragma unroll
                for (int s = 0; s < 8; s++) {
                    float cs = (float)((c >> (8 * s)) & 0xFF);
                    if (cs != 0.f) {
                        u64 vv = pack2(cs, cs);
#pragma unroll
                        for (int j = 0; j < 8; j++) fma2(ac[j], vv, sYdd[s * 8 + j]);
                    }
                }
            }
        }
        // root (5-dim, fp32 padded copy)
        {
            const float4* rp = (const float4*)(g_xd8 + (size_t)n * 8);
            float4 A = rp[0], B = rp[1];
            float a[5] = {A.x, A.y, A.z, A.w, B.x};
#pragma unroll
            for (int d = 0; d < 5; d++) {
                u64 vv = pack2(a[d], a[d]);
#pragma unroll
                for (int j = 0; j < 8; j++) fma2(ac[j], vv, sWrt5[d * 8 + j]);
            }
        }
        float av[16];
#pragma unroll
        for (int j = 0; j < 8; j++) {
            float2 f = unpack2(ac[j]);
            av[2 * j] = f.x; av[2 * j + 1] = f.y;
        }
        ln_act_store(av, smf + 16, smf + 32, out + (size_t)(NT + n) * 16);

    } else {
        // ---- devices (8 nodes) ----
        int n = t;
        if (n >= 8) return;
        float acc[16];
#pragma unroll
        for (int h = 0; h < 16; h++) acc[h] = b_rel[2 * 16 + h] + b_rel[4 * 16 + h];
        for (int d = 0; d < 12; d++) {
            float v = g_tdev[n * 12 + d];
#pragma unroll
            for (int h = 0; h < 16; h++) acc[h] += v * W_rel12[1 * 192 + d * 16 + h];
        }
        for (int d = 0; d < 5; d++) {
            float v = g_ddev[n * 8 + d];
#pragma unroll
            for (int h = 0; h < 16; h++) acc[h] += v * W_rel5[80 + d * 16 + h];
        }
        for (int d = 0; d < 12; d++) {
            float v = xv[n * 12 + d];
#pragma unroll
            for (int h = 0; h < 16; h++)
                acc[h] += v * (W_root12[1 * 192 + d * 16 + h] + W_root12[3 * 192 + d * 16 + h]);
        }
        float gam[16], bet[16];
#pragma unroll
        for (int h = 0; h < 16; h++) { gam[h] = ln_g[2 * 16 + h]; bet[h] = ln_b[2 * 16 + h]; }
        ln_act_store(acc, gam, bet, out + (size_t)(NT + ND + n) * 16);
    }
}

// ---------------- launch ----------------
extern "C" void kernel_launch(void* const* d_in, const int* in_sizes, int n_in,
                              void* d_out, int out_size) {
    const float* x_tasks = (const float*)d_in[0];
    const float* x_data  = (const float*)d_in[1];
    const float* x_dev   = (const float*)d_in[2];
    const int* ei_dt   = (const int*)d_in[3];   // data  -> tasks
    const int* ei_td   = (const int*)d_in[4];   // tasks -> data
    const int* ei_tdev = (const int*)d_in[5];   // tasks -> devices
    const int* ei_devt = (const int*)d_in[6];   // devices -> tasks
    const int* ei_ddev = (const int*)d_in[7];   // data  -> devices
    const int* ei_devd = (const int*)d_in[8];   // devices -> data
    const int* ei_tto  = (const int*)d_in[9];   // tasks -> tasks (to)
    const int* ei_ttf  = (const int*)d_in[10];  // tasks -> tasks (from)
    const float* W_rel5   = (const float*)d_in[11];
    const float* W_rel12  = (const float*)d_in[12];
    const float* b_rel    = (const float*)d_in[13];
    const float* W_root5  = (const float*)d_in[14];
    const float* W_root12 = (const float*)d_in[15];
    const float* ln_g     = (const float*)d_in[16];
    const float* ln_b     = (const float*)d_in[17];
    float* out = (float*)d_out;

    int E_dt   = in_sizes[3]  / 2;
    int E_td   = in_sizes[4]  / 2;
    int E_tdev = in_sizes[5]  / 2;
    int E_devt = in_sizes[6]  / 2;
    int E_ddev = in_sizes[7]  / 2;
    int E_devd = in_sizes[8]  / 2;
    int E_tto  = in_sizes[9]  / 2;
    int E_ttf  = in_sizes[10] / 2;

    auto cdiv = [](int a, int b) { return (a + b - 1) / b; };
    int b0 = cdiv(E_dt, 256);
    int b1 = b0 + cdiv(E_tto, 256);
    int b2 = b1 + cdiv(E_ttf, 256);
    int b3 = b2 + cdiv(E_td, 256);
    int b4 = b3 + cdiv(E_devt, 256);
    int b5 = b4 + cdiv(E_devd, 256);
    int b6 = b5 + cdiv(E_tdev, 256);
    int b7 = b6 + cdiv(E_ddev, 256);

    prep<<<1024, 256>>>(x_data, x_tasks);
    fused_scatter<<<b7, 256>>>(ei_dt, E_dt, ei_tto, E_tto, ei_ttf, E_ttf, ei_td, E_td,
                               ei_devt, E_devt, ei_devd, E_devd,
                               ei_tdev, E_tdev, ei_ddev, E_ddev,
                               b0, b1, b2, b3, b4, b5, b6);
    fused_node<<<NBT + NBD + 1, 256>>>(x_tasks, x_dev, W_rel5, W_rel12, b_rel,
                                       W_root5, W_root12, ln_g, ln_b, out);
}

// round 16
// speedup vs baseline: 1.2434x; 1.2035x over previous
#include <cuda_runtime.h>
#include <cuda_fp16.h>
#include <cstdint>

#define NT 400000
#define ND 200000

typedef unsigned long long u64;

// ---------------- static scratch (referenced ONLY from device code) ----------------
__device__ __align__(16) __half g_to16[(size_t)NT * 16];  // tt_to fp16 sums (12 used)  12.8MB
__device__ __align__(16) __half g_fr16[(size_t)NT * 16];  // tt_from fp16 sums          12.8MB
__device__ __align__(16) __half g_dt16[(size_t)NT * 8];   // data->tasks fp16 sums (5)   6.4MB
__device__ __align__(16) __half g_td16[(size_t)ND * 16];  // tasks->data fp16 sums       6.4MB
__device__ __align__(16) u64    g_cdevt[NT];              // devices->tasks 8x8bit cnt   3.2MB
__device__ __align__(16) u64    g_cdevd[ND];              // devices->data 8x8bit cnt    1.6MB
__device__ float g_tdev[8 * 12];                          // tasks->devices agg (fp32)
__device__ float g_ddev[8 * 8];                           // data->devices agg (fp32)
__device__ __align__(16) __half g_xt16[(size_t)NT * 16];  // x_tasks fp16, stride 16h   12.8MB
__device__ __align__(16) __half g_xd16[(size_t)ND * 8];   // x_data fp16, stride 8h      3.2MB

// ---------------- helpers ----------------
__device__ __forceinline__ u64 pack2(float x, float y) {
    u64 r; asm("mov.b64 %0, {%1,%2};" : "=l"(r) : "f"(x), "f"(y)); return r;
}
__device__ __forceinline__ float2 unpack2(u64 v) {
    float2 r; asm("mov.b64 {%0,%1}, %2;" : "=f"(r.x), "=f"(r.y) : "l"(v)); return r;
}
__device__ __forceinline__ void fma2(u64& d, u64 a, u64 b) {  // d = a*b + d (packed f32x2)
    asm("fma.rn.f32x2 %0, %1, %2, %0;" : "+l"(d) : "l"(a), "l"(b));
}
__device__ __forceinline__ void red1(float* p, float a) {
    asm volatile("red.global.add.f32 [%0], %1;" :: "l"(p), "f"(a) : "memory");
}
__device__ __forceinline__ void redu64(u64* p, u64 v) {
    asm volatile("red.global.add.u64 [%0], %1;" :: "l"(p), "l"(v) : "memory");
}
// vectorized fp16x2 reductions (sm_90+)
__device__ __forceinline__ void redh8(__half* p, unsigned a, unsigned b, unsigned c, unsigned d) {
    asm volatile("red.global.add.noftz.v4.f16x2 [%0], {%1,%2,%3,%4};"
                 :: "l"(p), "r"(a), "r"(b), "r"(c), "r"(d) : "memory");
}
__device__ __forceinline__ void redh4(__half* p, unsigned a, unsigned b) {
    asm volatile("red.global.add.noftz.v2.f16x2 [%0], {%1,%2};"
                 :: "l"(p), "r"(a), "r"(b) : "memory");
}
__device__ __forceinline__ unsigned h2u(__half2 h) {
    return *reinterpret_cast<unsigned*>(&h);
}
__device__ __forceinline__ float2 u2f(unsigned u) {
    __half2 h = *reinterpret_cast<__half2*>(&u);
    return __half22float2(h);
}

// ---------------- prep: zero scratch + build fp16 copies ----------------
__global__ void prep(const float* __restrict__ xd, const float* __restrict__ xt) {
    size_t i  = (size_t)blockIdx.x * blockDim.x + threadIdx.x;
    size_t st = (size_t)gridDim.x * blockDim.x;
    float4 z = make_float4(0.f, 0.f, 0.f, 0.f);
    for (size_t j = i; j < (size_t)NT * 2; j += st) ((float4*)g_to16)[j] = z;
    for (size_t j = i; j < (size_t)NT * 2; j += st) ((float4*)g_fr16)[j] = z;
    for (size_t j = i; j < (size_t)NT; j += st)     ((float4*)g_dt16)[j] = z;
    for (size_t j = i; j < (size_t)ND * 2; j += st) ((float4*)g_td16)[j] = z;
    for (size_t j = i; j < (size_t)NT / 2; j += st) ((float4*)g_cdevt)[j] = z;
    for (size_t j = i; j < (size_t)ND / 2; j += st) ((float4*)g_cdevd)[j] = z;
    if (i < 96) g_tdev[i] = 0.f;
    if (i < 64) g_ddev[i] = 0.f;
    // x_data fp16 copy (stride 8 halves = 16B, halves 5..7 zero)
    for (size_t j = i; j < (size_t)ND; j += st) {
        const float* r = xd + j * 5;
        uint4 u;
        u.x = h2u(__floats2half2_rn(r[0], r[1]));
        u.y = h2u(__floats2half2_rn(r[2], r[3]));
        u.z = h2u(__floats2half2_rn(r[4], 0.f));
        u.w = 0;
        *(uint4*)(g_xd16 + j * 8) = u;
    }
    // x_tasks fp16 copy (stride 16 halves = 32B, 12 used)
    for (size_t j = i; j < (size_t)NT; j += st) {
        const float4* r = (const float4*)(xt + j * 12);
        float4 a = r[0], b = r[1], c = r[2];
        uint4 ua;
        ua.x = h2u(__floats2half2_rn(a.x, a.y));
        ua.y = h2u(__floats2half2_rn(a.z, a.w));
        ua.z = h2u(__floats2half2_rn(b.x, b.y));
        ua.w = h2u(__floats2half2_rn(b.z, b.w));
        uint2 ub;
        ub.x = h2u(__floats2half2_rn(c.x, c.y));
        ub.y = h2u(__floats2half2_rn(c.z, c.w));
        __half* row = g_xt16 + j * 16;
        *(uint4*)row = ua;
        *(uint2*)(row + 8) = ub;
    }
}

// gather a 12-dim fp16 row into 12 floats (2 loads)
__device__ __forceinline__ void gather12h(int s, float* f) {
    const __half* row = g_xt16 + (size_t)s * 16;
    uint4 ua = *(const uint4*)row;
    uint2 ub = *(const uint2*)(row + 8);
    float2 f0 = u2f(ua.x), f1 = u2f(ua.y), f2 = u2f(ua.z);
    float2 f3 = u2f(ua.w), f4 = u2f(ub.x), f5 = u2f(ub.y);
    f[0] = f0.x; f[1] = f0.y; f[2]  = f1.x; f[3]  = f1.y;
    f[4] = f2.x; f[5] = f2.y; f[6]  = f3.x; f[7]  = f3.y;
    f[8] = f4.x; f[9] = f4.y; f[10] = f5.x; f[11] = f5.y;
}

// ---------------- fused scatter: all 8 relations, one launch (thread-per-edge) ----------------
__global__ void fused_scatter(
    const int* __restrict__ e_dt,   int E_dt,
    const int* __restrict__ e_to,   int E_to,
    const int* __restrict__ e_fr,   int E_fr,
    const int* __restrict__ e_td,   int E_td,
    const int* __restrict__ e_devt, int E_devt,
    const int* __restrict__ e_devd, int E_devd,
    const int* __restrict__ e_tdev, int E_tdev,
    const int* __restrict__ e_ddev, int E_ddev,
    int b0, int b1, int b2, int b3, int b4, int b5, int b6) {
    int b = blockIdx.x, t = threadIdx.x;

    if (b < b0) {                       // data -> tasks : 1 gather + 1 RED (pads add zero)
        int e = b * 256 + t;
        if (e >= E_dt) return;
        int s = e_dt[e], d = e_dt[E_dt + e];
        uint4 u = *(const uint4*)(g_xd16 + (size_t)s * 8);
        redh8(g_dt16 + (size_t)d * 8, u.x, u.y, u.z, u.w);
    } else if (b < b3) {                // 12-dim relations: tto | ttf | td : 2 gathers + 2 REDs
        const int* ei; int E; __half* acc; int rb;
        if (b < b1)      { ei = e_to; E = E_to; acc = g_to16; rb = b - b0; }
        else if (b < b2) { ei = e_fr; E = E_fr; acc = g_fr16; rb = b - b1; }
        else             { ei = e_td; E = E_td; acc = g_td16; rb = b - b2; }
        int e = rb * 256 + t;
        if (e >= E) return;
        int s = ei[e], d = ei[E + e];
        const __half* row = g_xt16 + (size_t)s * 16;
        uint4 ua = *(const uint4*)row;
        uint2 ub = *(const uint2*)(row + 8);
        __half* p = acc + (size_t)d * 16;
        redh8(p, ua.x, ua.y, ua.z, ua.w);
        redh4(p + 8, ub.x, ub.y);
    } else if (b < b4) {                // devices -> tasks : packed count
        int e = (b - b3) * 256 + t;
        if (e >= E_devt) return;
        int s = e_devt[e], d = e_devt[E_devt + e];
        redu64(&g_cdevt[d], 1ull << (s * 8));
    } else if (b < b5) {                // devices -> data : packed count
        int e = (b - b4) * 256 + t;
        if (e >= E_devd) return;
        int s = e_devd[e], d = e_devd[E_devd + e];
        redu64(&g_cdevd[d], 1ull << (s * 8));
    } else if (b < b6) {                // tasks -> devices (dst in [0,8)), fp32 smem
        __shared__ float acc[96];
        if (t < 96) acc[t] = 0.f;
        __syncthreads();
        int e = (b - b5) * 256 + t;
        if (e < E_tdev) {
            int s = e_tdev[e], d = e_tdev[E_tdev + e];
            float f[12];
            gather12h(s, f);
            float* a = acc + d * 12;
#pragma unroll
            for (int k = 0; k < 12; k++) atomicAdd(a + k, f[k]);
        }
        __syncthreads();
        if (t < 96 && acc[t] != 0.f) red1(&g_tdev[t], acc[t]);
    } else {                            // data -> devices (5-dim), fp32 smem
        __shared__ float acc[64];
        if (t < 64) acc[t] = 0.f;
        __syncthreads();
        int e = (b - b6) * 256 + t;
        if (e < E_ddev) {
            int s = e_ddev[e], d = e_ddev[E_ddev + e];
            uint4 u = *(const uint4*)(g_xd16 + (size_t)s * 8);
            float2 f0 = u2f(u.x), f1 = u2f(u.y), f2 = u2f(u.z);
            float* a = acc + d * 8;
            atomicAdd(a + 0, f0.x); atomicAdd(a + 1, f0.y);
            atomicAdd(a + 2, f1.x); atomicAdd(a + 3, f1.y);
            atomicAdd(a + 4, f2.x);
        }
        __syncthreads();
        if (t < 64 && acc[t] != 0.f) red1(&g_ddev[t], acc[t]);
    }
}

// ---------------- LN + leaky relu + store ----------------
__device__ __forceinline__ void ln_act_store(float* a, const float* gam, const float* bet,
                                             float* outp) {
    float mu = 0.f;
#pragma unroll
    for (int h = 0; h < 16; h++) mu += a[h];
    mu *= (1.f / 16.f);
    float var = 0.f;
#pragma unroll
    for (int h = 0; h < 16; h++) { float z = a[h] - mu; var += z * z; }
    var *= (1.f / 16.f);
    float inv = rsqrtf(var + 1e-5f);
    float4 o[4];
    float* of = (float*)o;
#pragma unroll
    for (int h = 0; h < 16; h++) {
        float y = (a[h] - mu) * inv * gam[h] + bet[h];
        of[h] = (y > 0.f) ? y : 0.01f * y;
    }
    float4* op = (float4*)outp;
#pragma unroll
    for (int q = 0; q < 4; q++) op[q] = o[q];
}

#define NBT ((NT + 255) / 256)   // 1563
#define NBD ((ND + 255) / 256)   // 782

// ---------------- fused node pass: tasks | data | devices ----------------
__global__ void fused_node(const float* __restrict__ xt,
                           const float* __restrict__ xv,
                           const float* __restrict__ W_rel5,
                           const float* __restrict__ W_rel12,
                           const float* __restrict__ b_rel,
                           const float* __restrict__ W_root5,
                           const float* __restrict__ W_root12,
                           const float* __restrict__ ln_g,
                           const float* __restrict__ ln_b,
                           float* __restrict__ out) {
    __shared__ __align__(16) u64 sm[392];
    __shared__ float smf[48];
    int bb = blockIdx.x, t = threadIdx.x;

    if (bb < NBT) {
        // ---- tasks ----
        u64* sW5  = sm;          // 40  : W_rel5[0]
        u64* sYd  = sm + 40;     // 64  : y_devt = x_dev @ W_rel12[2]  (8 x 16)
        u64* sWto = sm + 104;    // 96  : W_rel12[4]
        u64* sWfr = sm + 200;    // 96  : W_rel12[5]
        u64* sWrt = sm + 296;    // 96  : sum of W_root12[0,2,4,5]
        if (t < 40) sW5[t] = pack2(W_rel5[2 * t], W_rel5[2 * t + 1]);
        if (t < 96) {
            sWto[t] = pack2(W_rel12[4 * 192 + 2 * t], W_rel12[4 * 192 + 2 * t + 1]);
            sWfr[t] = pack2(W_rel12[5 * 192 + 2 * t], W_rel12[5 * 192 + 2 * t + 1]);
            float w0 = W_root12[2 * t] + W_root12[2 * 192 + 2 * t] +
                       W_root12[4 * 192 + 2 * t] + W_root12[5 * 192 + 2 * t];
            float w1 = W_root12[2 * t + 1] + W_root12[2 * 192 + 2 * t + 1] +
                       W_root12[4 * 192 + 2 * t + 1] + W_root12[5 * 192 + 2 * t + 1];
            sWrt[t] = pack2(w0, w1);
        }
        if (t < 64) {
            int n = t >> 3, h0 = (t & 7) * 2;
            float y0 = 0.f, y1 = 0.f;
#pragma unroll
            for (int d = 0; d < 12; d++) {
                float xvv = xv[n * 12 + d];
                y0 += xvv * W_rel12[2 * 192 + d * 16 + h0];
                y1 += xvv * W_rel12[2 * 192 + d * 16 + h0 + 1];
            }
            sYd[t] = pack2(y0, y1);
        }
        if (t < 16) {
            smf[t]      = b_rel[t] + b_rel[3 * 16 + t] + b_rel[6 * 16 + t] + b_rel[7 * 16 + t];
            smf[16 + t] = ln_g[t];
            smf[32 + t] = ln_b[t];
        }
        __syncthreads();
        int n = bb * 256 + t;
        if (n >= NT) return;

        u64 ac[8];
#pragma unroll
        for (int j = 0; j < 8; j++) ac[j] = pack2(smf[2 * j], smf[2 * j + 1]);

        // dt (5-dim fp16 sums)
        {
            uint4 u = *(const uint4*)(g_dt16 + (size_t)n * 8);
            float2 f0 = u2f(u.x), f1 = u2f(u.y), f2 = u2f(u.z);
            float a[5] = {f0.x, f0.y, f1.x, f1.y, f2.x};
#pragma unroll
            for (int d = 0; d < 5; d++) {
                u64 vv = pack2(a[d], a[d]);
#pragma unroll
                for (int j = 0; j < 8; j++) fma2(ac[j], vv, sW5[d * 8 + j]);
            }
        }
        // devt counts
        {
            u64 c = g_cdevt[n];
            if (c) {
#pragma unroll
                for (int s = 0; s < 8; s++) {
                    float cs = (float)((c >> (8 * s)) & 0xFF);
                    if (cs != 0.f) {
                        u64 vv = pack2(cs, cs);
#pragma unroll
                        for (int j = 0; j < 8; j++) fma2(ac[j], vv, sYd[s * 8 + j]);
                    }
                }
            }
        }
        // tt_to fp16 sums
        {
            const __half* row = g_to16 + (size_t)n * 16;
            uint4 ua = *(const uint4*)row;
            uint2 ub = *(const uint2*)(row + 8);
            float2 f0 = u2f(ua.x), f1 = u2f(ua.y), f2 = u2f(ua.z);
            float2 f3 = u2f(ua.w), f4 = u2f(ub.x), f5 = u2f(ub.y);
            float a[12] = {f0.x, f0.y, f1.x, f1.y, f2.x, f2.y,
                           f3.x, f3.y, f4.x, f4.y, f5.x, f5.y};
#pragma unroll
            for (int d = 0; d < 12; d++) {
                u64 vv = pack2(a[d], a[d]);
#pragma unroll
                for (int j = 0; j < 8; j++) fma2(ac[j], vv, sWto[d * 8 + j]);
            }
        }
        // tt_from fp16 sums
        {
            const __half* row = g_fr16 + (size_t)n * 16;
            uint4 ua = *(const uint4*)row;
            uint2 ub = *(const uint2*)(row + 8);
            float2 f0 = u2f(ua.x), f1 = u2f(ua.y), f2 = u2f(ua.z);
            float2 f3 = u2f(ua.w), f4 = u2f(ub.x), f5 = u2f(ub.y);
            float a[12] = {f0.x, f0.y, f1.x, f1.y, f2.x, f2.y,
                           f3.x, f3.y, f4.x, f4.y, f5.x, f5.y};
#pragma unroll
            for (int d = 0; d < 12; d++) {
                u64 vv = pack2(a[d], a[d]);
#pragma unroll
                for (int j = 0; j < 8; j++) fma2(ac[j], vv, sWfr[d * 8 + j]);
            }
        }
        // root (full fp32)
        {
            const float4* rp = (const float4*)(xt + (size_t)n * 12);
            float4 A = rp[0], B = rp[1], C = rp[2];
            float a[12] = {A.x, A.y, A.z, A.w, B.x, B.y, B.z, B.w, C.x, C.y, C.z, C.w};
#pragma unroll
            for (int d = 0; d < 12; d++) {
                u64 vv = pack2(a[d], a[d]);
#pragma unroll
                for (int j = 0; j < 8; j++) fma2(ac[j], vv, sWrt[d * 8 + j]);
            }
        }
        float av[16];
#pragma unroll
        for (int j = 0; j < 8; j++) {
            float2 f = unpack2(ac[j]);
            av[2 * j] = f.x; av[2 * j + 1] = f.y;
        }
        ln_act_store(av, smf + 16, smf + 32, out + (size_t)n * 16);

    } else if (bb < NBT + NBD) {
        // ---- data ----
        u64* sWtd  = sm;         // 96 : W_rel12[0]
        u64* sYdd  = sm + 96;    // 64 : y_devd = x_dev @ W_rel12[3]
        u64* sWrt5 = sm + 160;   // 40 : W_root5[0] + W_root5[1]
        if (t < 96) sWtd[t] = pack2(W_rel12[2 * t], W_rel12[2 * t + 1]);
        if (t < 64) {
            int n = t >> 3, h0 = (t & 7) * 2;
            float y0 = 0.f, y1 = 0.f;
#pragma unroll
            for (int d = 0; d < 12; d++) {
                float xvv = xv[n * 12 + d];
                y0 += xvv * W_rel12[3 * 192 + d * 16 + h0];
                y1 += xvv * W_rel12[3 * 192 + d * 16 + h0 + 1];
            }
            sYdd[t] = pack2(y0, y1);
        }
        if (t < 40) {
            float w0 = W_root5[2 * t]     + W_root5[80 + 2 * t];
            float w1 = W_root5[2 * t + 1] + W_root5[80 + 2 * t + 1];
            sWrt5[t] = pack2(w0, w1);
        }
        if (t < 16) {
            smf[t]      = b_rel[16 + t] + b_rel[5 * 16 + t];
            smf[16 + t] = ln_g[16 + t];
            smf[32 + t] = ln_b[16 + t];
        }
        __syncthreads();
        int n = (bb - NBT) * 256 + t;
        if (n >= ND) return;

        u64 ac[8];
#pragma unroll
        for (int j = 0; j < 8; j++) ac[j] = pack2(smf[2 * j], smf[2 * j + 1]);

        // td fp16 sums
        {
            const __half* row = g_td16 + (size_t)n * 16;
            uint4 ua = *(const uint4*)row;
            uint2 ub = *(const uint2*)(row + 8);
            float2 f0 = u2f(ua.x), f1 = u2f(ua.y), f2 = u2f(ua.z);
            float2 f3 = u2f(ua.w), f4 = u2f(ub.x), f5 = u2f(ub.y);
            float a[12] = {f0.x, f0.y, f1.x, f1.y, f2.x, f2.y,
                           f3.x, f3.y, f4.x, f4.y, f5.x, f5.y};
#pragma unroll
            for (int d = 0; d < 12; d++) {
                u64 vv = pack2(a[d], a[d]);
#pragma unroll
                for (int j = 0; j < 8; j++) fma2(ac[j], vv, sWtd[d * 8 + j]);
            }
        }
        // devd counts
        {
            u64 c = g_cdevd[n];
            if (c) {
#pragma unroll
                for (int s = 0; s < 8; s++) {
                    float cs = (float)((c >> (8 * s)) & 0xFF);
                    if (cs != 0.f) {
                        u64 vv = pack2(cs, cs);
#pragma unroll
                        for (int j = 0; j < 8; j++) fma2(ac[j], vv, sYdd[s * 8 + j]);
                    }
                }
            }
        }
        // root (5-dim, fp16 copy)
        {
            uint4 u = *(const uint4*)(g_xd16 + (size_t)n * 8);
            float2 f0 = u2f(u.x), f1 = u2f(u.y), f2 = u2f(u.z);
            float a[5] = {f0.x, f0.y, f1.x, f1.y, f2.x};
#pragma unroll
            for (int d = 0; d < 5; d++) {
                u64 vv = pack2(a[d], a[d]);
#pragma unroll
                for (int j = 0; j < 8; j++) fma2(ac[j], vv, sWrt5[d * 8 + j]);
            }
        }
        float av[16];
#pragma unroll
        for (int j = 0; j < 8; j++) {
            float2 f = unpack2(ac[j]);
            av[2 * j] = f.x; av[2 * j + 1] = f.y;
        }
        ln_act_store(av, smf + 16, smf + 32, out + (size_t)(NT + n) * 16);

    } else {
        // ---- devices (8 nodes) ----
        int n = t;
        if (n >= 8) return;
        float acc[16];
#pragma unroll
        for (int h = 0; h < 16; h++) acc[h] = b_rel[2 * 16 + h] + b_rel[4 * 16 + h];
        for (int d = 0; d < 12; d++) {
            float v = g_tdev[n * 12 + d];
#pragma unroll
            for (int h = 0; h < 16; h++) acc[h] += v * W_rel12[1 * 192 + d * 16 + h];
        }
        for (int d = 0; d < 5; d++) {
            float v = g_ddev[n * 8 + d];
#pragma unroll
            for (int h = 0; h < 16; h++) acc[h] += v * W_rel5[80 + d * 16 + h];
        }
        for (int d = 0; d < 12; d++) {
            float v = xv[n * 12 + d];
#pragma unroll
            for (int h = 0; h < 16; h++)
                acc[h] += v * (W_root12[1 * 192 + d * 16 + h] + W_root12[3 * 192 + d * 16 + h]);
        }
        float gam[16], bet[16];
#pragma unroll
        for (int h = 0; h < 16; h++) { gam[h] = ln_g[2 * 16 + h]; bet[h] = ln_b[2 * 16 + h]; }
        ln_act_store(acc, gam, bet, out + (size_t)(NT + ND + n) * 16);
    }
}

// ---------------- launch ----------------
extern "C" void kernel_launch(void* const* d_in, const int* in_sizes, int n_in,
                              void* d_out, int out_size) {
    const float* x_tasks = (const float*)d_in[0];
    const float* x_data  = (const float*)d_in[1];
    const float* x_dev   = (const float*)d_in[2];
    const int* ei_dt   = (const int*)d_in[3];   // data  -> tasks
    const int* ei_td   = (const int*)d_in[4];   // tasks -> data
    const int* ei_tdev = (const int*)d_in[5];   // tasks -> devices
    const int* ei_devt = (const int*)d_in[6];   // devices -> tasks
    const int* ei_ddev = (const int*)d_in[7];   // data  -> devices
    const int* ei_devd = (const int*)d_in[8];   // devices -> data
    const int* ei_tto  = (const int*)d_in[9];   // tasks -> tasks (to)
    const int* ei_ttf  = (const int*)d_in[10];  // tasks -> tasks (from)
    const float* W_rel5   = (const float*)d_in[11];
    const float* W_rel12  = (const float*)d_in[12];
    const float* b_rel    = (const float*)d_in[13];
    const float* W_root5  = (const float*)d_in[14];
    const float* W_root12 = (const float*)d_in[15];
    const float* ln_g     = (const float*)d_in[16];
    const float* ln_b     = (const float*)d_in[17];
    float* out = (float*)d_out;

    int E_dt   = in_sizes[3]  / 2;
    int E_td   = in_sizes[4]  / 2;
    int E_tdev = in_sizes[5]  / 2;
    int E_devt = in_sizes[6]  / 2;
    int E_ddev = in_sizes[7]  / 2;
    int E_devd = in_sizes[8]  / 2;
    int E_tto  = in_sizes[9]  / 2;
    int E_ttf  = in_sizes[10] / 2;

    auto cdiv = [](int a, int b) { return (a + b - 1) / b; };
    int b0 = cdiv(E_dt, 256);
    int b1 = b0 + cdiv(E_tto, 256);
    int b2 = b1 + cdiv(E_ttf, 256);
    int b3 = b2 + cdiv(E_td, 256);
    int b4 = b3 + cdiv(E_devt, 256);
    int b5 = b4 + cdiv(E_devd, 256);
    int b6 = b5 + cdiv(E_tdev, 256);
    int b7 = b6 + cdiv(E_ddev, 256);

    prep<<<1024, 256>>>(x_data, x_tasks);
    fused_scatter<<<b7, 256>>>(ei_dt, E_dt, ei_tto, E_tto, ei_ttf, E_ttf, ei_td, E_td,
                               ei_devt, E_devt, ei_devd, E_devd,
                               ei_tdev, E_tdev, ei_ddev, E_ddev,
                               b0, b1, b2, b3, b4, b5, b6);
    fused_node<<<NBT + NBD + 1, 256>>>(x_tasks, x_dev, W_rel5, W_rel12, b_rel,
                                       W_root5, W_root12, ln_g, ln_b, out);
}